// round 1
// baseline (speedup 1.0000x reference)
#include <cuda_runtime.h>
#include <cuda_bf16.h>

// DNM_Linear: out[b,o] = relu(K^2 * sum_{m,i} relu(x[b,i]*W[o,m,i] - q[o,m,i]) - K*QS)
// (inner relu(sum) is identity since summands are >= 0)
// x: [512, 512] f32, W/q: [128, 8, 512] f32 -> flat [1024, 512], out: [512, 128] f32

#define B_TOT   512
#define IN_DIM  512
#define NEUR    1024   // OUT * M
#define OUT_DIM 128
#define BT      64     // batch tile
#define NT      64     // neuron tile
#define KC      32     // k chunk
#define PAD     4

__global__ __launch_bounds__(256, 1)
void dnm_kernel(const float* __restrict__ x,
                const float* __restrict__ W,
                const float* __restrict__ q,
                float* __restrict__ out)
{
    __shared__ float sx[KC][BT + PAD];
    __shared__ float sw[KC][NT + PAD];
    __shared__ float sq[KC][NT + PAD];   // holds -q

    const int t  = threadIdx.x;
    const int n0 = blockIdx.x * NT;
    const int b0 = blockIdx.y * BT;

    // ---- global load mapping: 4 threads per row, 16 contiguous floats each (2 x float4)
    const int row = t >> 2;          // 0..63 (tile row: batch for x, neuron for W/q)
    const int kq  = (t & 3) * 4;     // 0,4,8,12

    const float* xg = x + (size_t)(b0 + row) * IN_DIM + kq;
    const float* wg = W + (size_t)(n0 + row) * IN_DIM + kq;
    const float* qg = q + (size_t)(n0 + row) * IN_DIM + kq;

    // ---- compute mapping: 16x16 thread grid, 4x4 per thread
    const int tx = t & 15;           // neuron cols: tx*4 .. tx*4+3
    const int ty = t >> 4;           // batch rows:  ty*4 .. ty*4+3

    float acc[4][4];
#pragma unroll
    for (int r = 0; r < 4; r++)
#pragma unroll
        for (int j = 0; j < 4; j++) acc[r][j] = 0.f;

    // prefetch chunk 0
    float4 px[2], pw[2], pq[2];
#pragma unroll
    for (int h = 0; h < 2; h++) {
        px[h] = *(const float4*)(xg + h * 16);
        pw[h] = *(const float4*)(wg + h * 16);
        pq[h] = *(const float4*)(qg + h * 16);
    }

    for (int kc = 0; kc < IN_DIM; kc += KC) {
        // store current chunk to shared (transposed), q negated
#pragma unroll
        for (int h = 0; h < 2; h++) {
            const int kb = kq + h * 16;
            float xv[4] = {px[h].x, px[h].y, px[h].z, px[h].w};
            float wv[4] = {pw[h].x, pw[h].y, pw[h].z, pw[h].w};
            float qv[4] = {pq[h].x, pq[h].y, pq[h].z, pq[h].w};
#pragma unroll
            for (int j = 0; j < 4; j++) {
                sx[kb + j][row] = xv[j];
                sw[kb + j][row] = wv[j];
                sq[kb + j][row] = -qv[j];
            }
        }
        __syncthreads();

        // prefetch next chunk (LDGs overlap with compute below)
        if (kc + KC < IN_DIM) {
            const int kn = kc + KC;
#pragma unroll
            for (int h = 0; h < 2; h++) {
                px[h] = *(const float4*)(xg + kn + h * 16);
                pw[h] = *(const float4*)(wg + kn + h * 16);
                pq[h] = *(const float4*)(qg + kn + h * 16);
            }
        }

        // compute
#pragma unroll 8
        for (int k = 0; k < KC; k++) {
            float4 xv = *(const float4*)&sx[k][ty * 4];
            float4 wv = *(const float4*)&sw[k][tx * 4];
            float4 qv = *(const float4*)&sq[k][tx * 4];
            float xr[4] = {xv.x, xv.y, xv.z, xv.w};
            float wr[4] = {wv.x, wv.y, wv.z, wv.w};
            float qr[4] = {qv.x, qv.y, qv.z, qv.w};
#pragma unroll
            for (int r = 0; r < 4; r++) {
#pragma unroll
                for (int j = 0; j < 4; j++) {
                    float v = fmaf(xr[r], wr[j], qr[j]);   // x*W - q
                    acc[r][j] += fmaxf(v, 0.f);
                }
            }
        }
        __syncthreads();
    }

    // ---- epilogue: fold 8 neurons (m) per output; thread pair (tx, tx^1) covers one o
#pragma unroll
    for (int r = 0; r < 4; r++) {
        float s = acc[r][0] + acc[r][1] + acc[r][2] + acc[r][3];
        float other = __shfl_xor_sync(0xffffffffu, s, 1);
        float raw8 = s + other;                       // sum over m = 0..7
        if ((tx & 1) == 0) {
            int b = b0 + ty * 4 + r;
            int o = (n0 >> 3) + (tx >> 1);
            // relu(0.5*(0.5*raw - 0.1)) = relu(0.25*raw - 0.05)
            out[b * OUT_DIM + o] = fmaxf(0.25f * raw8 - 0.05f, 0.f);
        }
    }
}

extern "C" void kernel_launch(void* const* d_in, const int* in_sizes, int n_in,
                              void* d_out, int out_size)
{
    const float* x = (const float*)d_in[0];
    const float* W = (const float*)d_in[1];
    const float* q = (const float*)d_in[2];
    float* out = (float*)d_out;

    dim3 grid(NEUR / NT, B_TOT / BT);   // 16 x 8 = 128 CTAs
    dnm_kernel<<<grid, 256>>>(x, W, q, out);
}